// round 8
// baseline (speedup 1.0000x reference)
#include <cuda_runtime.h>
#include <cuda_bf16.h>
#include <cstdint>

// B=128, U=64, A=64. GEMMs: bf16 mma.sync m16n8k16, 3-term hi/lo emulation.
// Intermediates PACKED bf16 hi/lo: slice = [plane(2)][pair_c(32)][u(64)] u32.
// Persistent CTAs + cp.async double-buffered X; W2 fragments in registers.

#define NBA 8192

__device__ __align__(16) uint32_t g_cgPh[NBA * 64];
__device__ __align__(16) uint32_t g_cgPl[NBA * 64];
__device__ __align__(16) uint32_t g_rP[(size_t)NBA * 4096];
__device__ __align__(16) uint32_t g_msgsP[(size_t)NBA * 4096];
__device__ float g_sums[128 * 4096];
__device__ float g_P[128 * 4096];
__device__ __align__(16) uint32_t g_wfrag[96256];

#define OFF_PHI1_W1F 0
#define OFF_PHI1_W2F 1024
#define OFF_PHIK_W1F 5120
#define OFF_PHIK_W2F 25600
#define OFF_G1_W1F   41984
#define OFF_G1_W2F   47104
#define OFF_GK_W1F   51200
#define OFF_GK_W2F   75776
#define OFF_G5_W1F   88064

#define CP_ASYNC16(dst, src) asm volatile("cp.async.cg.shared.global [%0], [%1], 16;" :: "r"(dst), "l"(src))
#define CP_COMMIT()          asm volatile("cp.async.commit_group;" ::: "memory")
#define CP_WAIT1()           asm volatile("cp.async.wait_group 1;" ::: "memory")
#define CP_WAIT0()           asm volatile("cp.async.wait_group 0;" ::: "memory")

__device__ __forceinline__ uint32_t pack2(float a, float b) {
    uint32_t la = (uint32_t)__bfloat16_as_ushort(__float2bfloat16_rn(a));
    uint32_t lb = (uint32_t)__bfloat16_as_ushort(__float2bfloat16_rn(b));
    return la | (lb << 16);
}
__device__ __forceinline__ void split1(float v, float& hi, float& lo) {
    hi = __bfloat162float(__float2bfloat16_rn(v));
    lo = v - hi;
}
__device__ __forceinline__ void mma16816(float d[4], const uint4& a, uint32_t b0, uint32_t b1) {
    asm volatile("mma.sync.aligned.m16n8k16.row.col.f32.bf16.bf16.f32 "
                 "{%0,%1,%2,%3}, {%4,%5,%6,%7}, {%8,%9}, {%0,%1,%2,%3};\n"
                 : "+f"(d[0]), "+f"(d[1]), "+f"(d[2]), "+f"(d[3])
                 : "r"(a.x), "r"(a.y), "r"(a.z), "r"(a.w), "r"(b0), "r"(b1));
}

// ---------------- prep: bf16 hi/lo A-fragments (verified in R4-R6) ----------
__global__ void prep_kernel(const float* __restrict__ phi1W1, const float* __restrict__ phi1W2,
                            const float* __restrict__ phiKW1, const float* __restrict__ phiKW2,
                            const float* __restrict__ g1W1,   const float* __restrict__ g1W2,
                            const float* __restrict__ gKW1,   const float* __restrict__ gKW2,
                            const float* __restrict__ g5W1) {
    const int id = blockIdx.x;
    const float* src; int off, KB, type;
    if (id == 0)       { src = phi1W1;              off = OFF_PHI1_W1F;            KB = 1; type = 3; }
    else if (id == 1)  { src = phi1W2;              off = OFF_PHI1_W2F;            KB = 4; type = 0; }
    else if (id < 6)   { int i = id - 2;  src = phiKW1 + i * 64 * 65;  off = OFF_PHIK_W1F + i * 5120; KB = 5; type = 1; }
    else if (id < 10)  { int i = id - 6;  src = phiKW2 + i * 4096;     off = OFF_PHIK_W2F + i * 4096; KB = 4; type = 0; }
    else if (id == 10) { src = g1W1;                off = OFF_G1_W1F;              KB = 5; type = 4; }
    else if (id == 11) { src = g1W2;                off = OFF_G1_W2F;              KB = 4; type = 0; }
    else if (id < 15)  { int i = id - 12; src = gKW1 + i * 64 * 128;   off = OFF_GK_W1F + i * 8192;   KB = 8; type = 5; }
    else if (id < 18)  { int i = id - 15; src = gKW2 + i * 4096;       off = OFF_GK_W2F + i * 4096;   KB = 4; type = 0; }
    else               { src = g5W1;                off = OFF_G5_W1F;              KB = 8; type = 5; }

    const float ninv = -1.0f / 63.0f;
    const int total = KB * 1024;
    for (int e = threadIdx.x; e < total; e += blockDim.x) {
        int strip = e / (KB * 256);
        int rem   = e % (KB * 256);
        int kt = rem / 256;
        int r2 = rem % 256;
        int plane = r2 >> 7;
        int r3 = r2 & 127;
        int lane = r3 >> 2, j = r3 & 3;
        int o  = strip * 16 + (lane >> 2) + 8 * (j & 1);
        int k0 = kt * 16 + (lane & 3) * 2 + 8 * (j >> 1);
        float w0, w1;
        if (type == 0)      { w0 = src[o * 64 + k0];  w1 = src[o * 64 + k0 + 1]; }
        else if (type == 5) { w0 = src[o * 128 + k0]; w1 = src[o * 128 + k0 + 1];
                              if (k0 >= 64) { w0 *= ninv; w1 *= ninv; } }
        else if (type == 1 || type == 4) {
            auto fetch = [&](int c) -> float {
                if (c < 64) {
                    float v = src[o * 65 + 1 + c];
                    return (type == 4) ? v * ninv : v;
                }
                if (c == 64) return src[o * 65];
                return 0.0f;
            };
            w0 = fetch(k0); w1 = fetch(k0 + 1);
        } else {
            w0 = (k0 == 0) ? (src[o * 2] + src[o * 2 + 1]) : 0.0f;
            w1 = 0.0f;
        }
        float h0, l0, h1, l1; split1(w0, h0, l0); split1(w1, h1, l1);
        g_wfrag[off + e] = plane ? pack2(l0, l1) : pack2(h0, h1);
    }
}

// ---------------- cg transpose + pack ----------------------------------------
__global__ void cgt_kernel(const float* __restrict__ cg) {
    const int b = blockIdx.x;
    for (int j = threadIdx.x; j < 4096; j += 256) {
        int a = j >> 6, u = j & 63;
        float v = cg[b * 4096 + u * 64 + a];
        uint32_t bits = __float_as_uint(v);
        float lo = v - __uint_as_float(bits & 0xffff0000u);
        g_cgPh[(b * 64 + a) * 64 + u] = bits >> 16;
        g_cgPl[(b * 64 + a) * 64 + u] = (uint32_t)__bfloat16_as_ushort(__float2bfloat16_rn(lo));
    }
}

// ---------------- sum over a of packed msgs -----------------------------------
__global__ void asum_kernel() {
    const int b = blockIdx.x >> 3;
    const int e = (blockIdx.x & 7) * 256 + threadIdx.x;
    const uint32_t* p0 = g_msgsP + (size_t)b * 262144 + e;
    float s0 = 0.f, s1 = 0.f;
#pragma unroll 4
    for (int a = 0; a < 64; ++a) {
        uint32_t h = p0[(size_t)a * 4096];
        uint32_t l = p0[(size_t)a * 4096 + 2048];
        s0 += __uint_as_float(h << 16) + __uint_as_float(l << 16);
        s1 += __uint_as_float(h & 0xffff0000u) + __uint_as_float(l & 0xffff0000u);
    }
    int pr = e >> 6, u = e & 63;
    g_sums[b * 4096 + (2 * pr) * 64 + u]     = s0;
    g_sums[b * 4096 + (2 * pr + 1) * 64 + u] = s1;
}

// ---------------- per-b precompute: P = bias1 + (Wagg/63)*S -------------------
__global__ void pP_kernel(const float* __restrict__ Wsrc, const float* __restrict__ b1,
                          int CW, int cOff) {
    __shared__ float sWT[64 * 65];
    __shared__ float sS2[4096];
    const int b = blockIdx.x, t = threadIdx.x;
    for (int idx = t; idx < 4096; idx += 256) {
        int o = idx >> 6, c = idx & 63;
        sWT[c * 65 + o] = Wsrc[o * CW + cOff + c] * (1.0f / 63.0f);
        sS2[idx] = g_sums[b * 4096 + idx];
    }
    __syncthreads();
    const int o = t & 63, ublk = t >> 6;
    float acc[16];
    float bv = __ldg(b1 + o);
#pragma unroll
    for (int i = 0; i < 16; ++i) acc[i] = bv;
    const float4* S4 = (const float4*)sS2;
#pragma unroll 4
    for (int c = 0; c < 64; ++c) {
        float w = sWT[c * 65 + o];
#pragma unroll
        for (int i = 0; i < 4; ++i) {
            float4 s = S4[c * 16 + ublk * 4 + i];
            acc[i * 4 + 0] += w * s.x; acc[i * 4 + 1] += w * s.y;
            acc[i * 4 + 2] += w * s.z; acc[i * 4 + 3] += w * s.w;
        }
    }
    float4* P4 = (float4*)(g_P + b * 4096 + o * 64 + ublk * 16);
#pragma unroll
    for (int i = 0; i < 4; ++i)
        P4[i] = make_float4(acc[i * 4], acc[i * 4 + 1], acc[i * 4 + 2], acc[i * 4 + 3]);
}

// ---------------- cp.async prefetch of one slice into an X buffer -------------
template<int MODE, int XR>
__device__ __forceinline__ void prefetch_slice(uint32_t dstH, uint32_t dstL, int ba, int t) {
    const uint32_t* rP = g_rP + (size_t)ba * 4096;
    const uint32_t* mP = g_msgsP + (size_t)ba * 4096;
    const uint32_t* ch = g_cgPh + ba * 64;
    const uint32_t* cl = g_cgPl + ba * 64;
    constexpr int NR = (MODE == 0) ? 1 : (MODE == 3) ? 64 : 33;
    for (int cc = t; cc < 2 * NR * 16; cc += 256) {
        int plane = cc / (NR * 16);
        int rr = cc % (NR * 16);
        int row = rr >> 4, c4 = (rr & 15) * 4;
        const uint32_t* src;
        if (MODE == 0) {
            src = (plane ? cl : ch) + c4;
        } else if (MODE == 3) {
            if (row < 32) src = rP + plane * 2048 + row * 64 + c4;
            else          src = mP + (plane ? 2048 : 0) + (row - 32) * 64 + c4;
        } else {
            const uint32_t* base = (MODE == 1) ? rP : mP;
            if (row < 32) src = base + plane * 2048 + row * 64 + c4;
            else          src = (plane ? cl : ch) + c4;     // row == 32
        }
        uint32_t dst = (plane ? dstL : dstH) + (uint32_t)(row * 72 + c4) * 4u;
        CP_ASYNC16(dst, src);
    }
}

// ---------------- layer kernel (persistent, double-buffered) ------------------
// MODE: 0 phi1, 1 phiK, 2 gamma1, 3 gammaK/gamma5
template<int KB1, int MODE, bool FINAL>
__global__ void __launch_bounds__(256, 2) layer_kernel(const float* __restrict__ b1v,
                                                       const float* __restrict__ b2v,
                                                       int w1off, int w2off,
                                                       const float* __restrict__ w2raw,
                                                       float* __restrict__ dout) {
    constexpr bool RELU2 = (MODE >= 2);
    constexpr bool DB = !FINAL;
    constexpr int XR = (KB1 * 8 < 32) ? 32 : KB1 * 8;
    constexpr int BUFU = 2 * XR * 72;                     // u32 per buffer (both planes)
    extern __shared__ uint32_t sm[];
    uint32_t* sW1f = sm;                                  // KB1*1024
    uint32_t* sX   = sW1f + KB1 * 1024;                   // (DB?2:1) * BUFU
    float*    sS   = (float*)(sX + (DB ? 2 : 1) * BUFU);  // 160
    float*    sH   = sS + 160;                            // 64*66 (FINAL only)

    const int t = threadIdx.x;
    const int warp = t >> 5, lane = t & 31, q = lane & 3, g = lane >> 2;
    const int s = warp >> 1, h2 = warp & 1;
    const int ub = h2 * 32;
    const int o_r = s * 16 + g, o_r8 = o_r + 8;
    const bool geven = ((g & 1) == 0);
    const float inv = 1.0f / 63.0f;

    uint32_t smbase;
    asm("{ .reg .u64 tmp; cvta.to.shared.u64 tmp, %1; cvt.u32.u64 %0, tmp; }"
        : "=r"(smbase) : "l"(sm));
    const uint32_t xbase = smbase + (uint32_t)(KB1 * 1024) * 4u;

    // W1 to smem; W2 fragments to registers
    {
        const uint4* gw1 = (const uint4*)(g_wfrag + w1off);
        uint4* d1 = (uint4*)sW1f;
        for (int i = t; i < KB1 * 256; i += 256) d1[i] = gw1[i];
    }
    uint4 W2h[4], W2l[4];
    if (!FINAL) {
        const uint4* gw2 = (const uint4*)(g_wfrag + w2off);
#pragma unroll
        for (int kt = 0; kt < 4; ++kt) {
            W2h[kt] = gw2[s * 256 + kt * 64 + lane];
            W2l[kt] = gw2[s * 256 + kt * 64 + 32 + lane];
        }
    }
    float bA1 = 0.f, bB1 = 0.f, bA2 = 0.f, bB2 = 0.f;
    if (MODE < 2) { bA1 = __ldg(b1v + o_r); bB1 = __ldg(b1v + o_r8); }
    if (!FINAL)   { bA2 = __ldg(b2v + o_r); bB2 = __ldg(b2v + o_r8); }

    // prezero X buffers (pad rows persist as zero)
    for (int i = t; i < (DB ? 2 : 1) * BUFU; i += 256) sX[i] = 0;
    __syncthreads();

    const int stride = gridDim.x;
    int o = 0;
    if (DB) {
        if ((int)blockIdx.x < NBA)
            prefetch_slice<MODE, XR>(xbase, xbase + XR * 72 * 4, blockIdx.x, t);
        CP_COMMIT();
    }

    for (int ba = blockIdx.x; ba < NBA; ba += stride) {
        const int b = ba >> 6;
        if (DB) {
            int nxt = ba + stride;
            uint32_t nb = xbase + (uint32_t)((o ^ 1) * BUFU) * 4u;
            if (nxt < NBA) prefetch_slice<MODE, XR>(nb, nb + XR * 72 * 4, nxt, t);
            CP_COMMIT();
            CP_WAIT1();
        } else {
            prefetch_slice<MODE, XR>(xbase, xbase + XR * 72 * 4, ba, t);
            CP_COMMIT();
            CP_WAIT0();
        }
        __syncthreads();

        uint32_t* bH = sX + o * BUFU;
        uint32_t* bL = bH + XR * 72;

        // early P loads (consumed post-mma)
        float2 pa[4], pb[4];
        if (MODE >= 2) {
            const float* Pb = g_P + b * 4096;
#pragma unroll
            for (int nt = 0; nt < 4; ++nt) {
                int u0 = ub + nt * 8 + q * 2;
                pa[nt] = __ldg((const float2*)(Pb + o_r * 64 + u0));
                pb[nt] = __ldg((const float2*)(Pb + o_r8 * 64 + u0));
            }
        }

        // ---- conv1 ----
        float acc[4][4];
#pragma unroll
        for (int nt = 0; nt < 4; ++nt)
#pragma unroll
            for (int j = 0; j < 4; ++j) acc[nt][j] = 0.f;
        {
            const uint4* A1 = (const uint4*)sW1f + s * (KB1 * 64);
#pragma unroll
            for (int kt = 0; kt < KB1; ++kt) {
                uint4 Ah = A1[kt * 64 + lane];
                uint4 Al = A1[kt * 64 + 32 + lane];
                const uint32_t* xh0 = bH + (kt * 8 + q) * 72 + ub + g;
                const uint32_t* xh1 = bH + (kt * 8 + 4 + q) * 72 + ub + g;
                const uint32_t* xl0 = bL + (kt * 8 + q) * 72 + ub + g;
                const uint32_t* xl1 = bL + (kt * 8 + 4 + q) * 72 + ub + g;
                uint32_t bh0[4], bh1[4], bl0[4], bl1[4];
#pragma unroll
                for (int nt = 0; nt < 4; ++nt) {
                    bh0[nt] = xh0[nt * 8]; bh1[nt] = xh1[nt * 8];
                    bl0[nt] = xl0[nt * 8]; bl1[nt] = xl1[nt * 8];
                }
#pragma unroll
                for (int nt = 0; nt < 4; ++nt) {
                    mma16816(acc[nt], Ah, bh0[nt], bh1[nt]);
                    mma16816(acc[nt], Ah, bl0[nt], bl1[nt]);
                    mma16816(acc[nt], Al, bh0[nt], bh1[nt]);
                }
            }
        }
        // bias/P (post-mma) + relu + colsum
        if (MODE >= 2) {
#pragma unroll
            for (int nt = 0; nt < 4; ++nt) {
                acc[nt][0] += pa[nt].x; acc[nt][1] += pa[nt].y;
                acc[nt][2] += pb[nt].x; acc[nt][3] += pb[nt].y;
            }
        } else {
#pragma unroll
            for (int nt = 0; nt < 4; ++nt) {
                acc[nt][0] += bA1; acc[nt][1] += bA1;
                acc[nt][2] += bB1; acc[nt][3] += bB1;
            }
        }
#pragma unroll
        for (int nt = 0; nt < 4; ++nt)
#pragma unroll
            for (int j = 0; j < 4; ++j) acc[nt][j] = fmaxf(acc[nt][j], 0.0f);
        {
            float sA = 0.f, sB = 0.f;
#pragma unroll
            for (int nt = 0; nt < 4; ++nt) { sA += acc[nt][0] + acc[nt][1]; sB += acc[nt][2] + acc[nt][3]; }
            sA += __shfl_xor_sync(0xffffffffu, sA, 1); sA += __shfl_xor_sync(0xffffffffu, sA, 2);
            sB += __shfl_xor_sync(0xffffffffu, sB, 1); sB += __shfl_xor_sync(0xffffffffu, sB, 2);
            if (q == 0) { sS[h2 * 80 + o_r] = sA; sS[h2 * 80 + o_r8] = sB; }
        }
        __syncthreads();
        float SA = sS[o_r] + sS[80 + o_r];
        float SB = sS[o_r8] + sS[80 + o_r8];

        if (!FINAL) {
            // post + pair-pack into current buffer rows 0..31
#pragma unroll
            for (int nt = 0; nt < 4; ++nt) {
                float t0, t1, t2, t3;
                if (s >= 2) {
                    t0 = (SA - acc[nt][0]) * inv; t1 = (SA - acc[nt][1]) * inv;
                    t2 = (SB - acc[nt][2]) * inv; t3 = (SB - acc[nt][3]) * inv;
                } else { t0 = acc[nt][0]; t1 = acc[nt][1]; t2 = acc[nt][2]; t3 = acc[nt][3]; }
                float p0 = __shfl_xor_sync(0xffffffffu, t0, 4);
                float p1 = __shfl_xor_sync(0xffffffffu, t1, 4);
                float p2 = __shfl_xor_sync(0xffffffffu, t2, 4);
                float p3 = __shfl_xor_sync(0xffffffffu, t3, 4);
                float v0a, v0b, v1a, v1b; int c2;
                if (geven) { c2 = (s * 16 + g) >> 1;          v0a = t0; v0b = p0; v1a = t1; v1b = p1; }
                else       { c2 = (s * 16 + 8 + g - 1) >> 1;  v0a = p2; v0b = t2; v1a = p3; v1b = t3; }
                uint32_t ba0 = __float_as_uint(v0a), bb0 = __float_as_uint(v0b);
                uint32_t ba1 = __float_as_uint(v1a), bb1 = __float_as_uint(v1b);
                uint32_t ph0 = __byte_perm(ba0, bb0, 0x7632);
                uint32_t ph1 = __byte_perm(ba1, bb1, 0x7632);
                float l0a = v0a - __uint_as_float(ba0 & 0xffff0000u);
                float l0b = v0b - __uint_as_float(bb0 & 0xffff0000u);
                float l1a = v1a - __uint_as_float(ba1 & 0xffff0000u);
                float l1b = v1b - __uint_as_float(bb1 & 0xffff0000u);
                uint32_t pl0 = pack2(l0a, l0b);
                uint32_t pl1 = pack2(l1a, l1b);
                int u0 = ub + nt * 8 + q * 2;
                bH[c2 * 72 + u0] = ph0; bH[c2 * 72 + u0 + 1] = ph1;
                bL[c2 * 72 + u0] = pl0; bL[c2 * 72 + u0 + 1] = pl1;
            }
            __syncthreads();

            // ---- conv2 (KB=4, W2 in registers) ----
            float a2[4][4];
#pragma unroll
            for (int nt = 0; nt < 4; ++nt)
#pragma unroll
                for (int j = 0; j < 4; ++j) a2[nt][j] = 0.f;
#pragma unroll
            for (int kt = 0; kt < 4; ++kt) {
                const uint32_t* xh0 = bH + (kt * 8 + q) * 72 + ub + g;
                const uint32_t* xh1 = bH + (kt * 8 + 4 + q) * 72 + ub + g;
                const uint32_t* xl0 = bL + (kt * 8 + q) * 72 + ub + g;
                const uint32_t* xl1 = bL + (kt * 8 + 4 + q) * 72 + ub + g;
                uint32_t bh0[4], bh1[4], bl0[4], bl1[4];
#pragma unroll
                for (int nt = 0; nt < 4; ++nt) {
                    bh0[nt] = xh0[nt * 8]; bh1[nt] = xh1[nt * 8];
                    bl0[nt] = xl0[nt * 8]; bl1[nt] = xl1[nt * 8];
                }
#pragma unroll
                for (int nt = 0; nt < 4; ++nt) {
                    mma16816(a2[nt], W2h[kt], bh0[nt], bh1[nt]);
                    mma16816(a2[nt], W2h[kt], bl0[nt], bl1[nt]);
                    mma16816(a2[nt], W2l[kt], bh0[nt], bh1[nt]);
                }
            }
#pragma unroll
            for (int nt = 0; nt < 4; ++nt) {
                a2[nt][0] += bA2; a2[nt][1] += bA2;
                a2[nt][2] += bB2; a2[nt][3] += bB2;
            }
            if (RELU2) {
#pragma unroll
                for (int nt = 0; nt < 4; ++nt)
#pragma unroll
                    for (int j = 0; j < 4; ++j) a2[nt][j] = fmaxf(a2[nt][j], 0.0f);
            }
            float s2A = 0.f, s2B = 0.f;
#pragma unroll
            for (int nt = 0; nt < 4; ++nt) { s2A += a2[nt][0] + a2[nt][1]; s2B += a2[nt][2] + a2[nt][3]; }
            s2A += __shfl_xor_sync(0xffffffffu, s2A, 1); s2A += __shfl_xor_sync(0xffffffffu, s2A, 2);
            s2B += __shfl_xor_sync(0xffffffffu, s2B, 1); s2B += __shfl_xor_sync(0xffffffffu, s2B, 2);
            if (q == 0) { sS[h2 * 80 + o_r] = s2A; sS[h2 * 80 + o_r8] = s2B; }
            __syncthreads();
            float S2A = sS[o_r] + sS[80 + o_r];
            float S2B = sS[o_r8] + sS[80 + o_r8];

            uint32_t* gout = (RELU2 ? g_rP : g_msgsP) + (size_t)ba * 4096;
#pragma unroll
            for (int nt = 0; nt < 4; ++nt) {
                float t0, t1, t2, t3;
                if (s >= 2) {
                    t0 = (S2A - a2[nt][0]) * inv; t1 = (S2A - a2[nt][1]) * inv;
                    t2 = (S2B - a2[nt][2]) * inv; t3 = (S2B - a2[nt][3]) * inv;
                } else { t0 = a2[nt][0]; t1 = a2[nt][1]; t2 = a2[nt][2]; t3 = a2[nt][3]; }
                float p0 = __shfl_xor_sync(0xffffffffu, t0, 4);
                float p1 = __shfl_xor_sync(0xffffffffu, t1, 4);
                float p2 = __shfl_xor_sync(0xffffffffu, t2, 4);
                float p3 = __shfl_xor_sync(0xffffffffu, t3, 4);
                float v0a, v0b, v1a, v1b; int c2;
                if (geven) { c2 = (s * 16 + g) >> 1;          v0a = t0; v0b = p0; v1a = t1; v1b = p1; }
                else       { c2 = (s * 16 + 8 + g - 1) >> 1;  v0a = p2; v0b = t2; v1a = p3; v1b = t3; }
                uint32_t ba0 = __float_as_uint(v0a), bb0 = __float_as_uint(v0b);
                uint32_t ba1 = __float_as_uint(v1a), bb1 = __float_as_uint(v1b);
                uint32_t ph0 = __byte_perm(ba0, bb0, 0x7632);
                uint32_t ph1 = __byte_perm(ba1, bb1, 0x7632);
                float l0a = v0a - __uint_as_float(ba0 & 0xffff0000u);
                float l0b = v0b - __uint_as_float(bb0 & 0xffff0000u);
                float l1a = v1a - __uint_as_float(ba1 & 0xffff0000u);
                float l1b = v1b - __uint_as_float(bb1 & 0xffff0000u);
                uint32_t pl0 = pack2(l0a, l0b);
                uint32_t pl1 = pack2(l1a, l1b);
                int u0 = ub + nt * 8 + q * 2;
                uint2 vh; vh.x = ph0; vh.y = ph1;
                uint2 vl; vl.x = pl0; vl.y = pl1;
                *(uint2*)(gout + c2 * 64 + u0) = vh;
                *(uint2*)(gout + 2048 + c2 * 64 + u0) = vl;
            }
            o ^= 1;
        } else {
            // FINAL: post-transformed H to sH, then 1x64 GEMV
#pragma unroll
            for (int nt = 0; nt < 4; ++nt) {
                int u0 = ub + nt * 8 + q * 2;
                float2 vA, vB;
                if (s >= 2) {
                    vA.x = (SA - acc[nt][0]) * inv; vA.y = (SA - acc[nt][1]) * inv;
                    vB.x = (SB - acc[nt][2]) * inv; vB.y = (SB - acc[nt][3]) * inv;
                } else { vA.x = acc[nt][0]; vA.y = acc[nt][1]; vB.x = acc[nt][2]; vB.y = acc[nt][3]; }
                *(float2*)(sH + o_r * 66 + u0)  = vA;
                *(float2*)(sH + o_r8 * 66 + u0) = vB;
            }
            __syncthreads();
            const int u = t >> 2, part = t & 3;
            float sv = 0.0f;
            const int c0 = part * 16;
#pragma unroll
            for (int c = c0; c < c0 + 16; ++c)
                sv = fmaf(__ldg(w2raw + c), sH[c * 66 + u], sv);
            sv += __shfl_xor_sync(0xffffffffu, sv, 1);
            sv += __shfl_xor_sync(0xffffffffu, sv, 2);
            if (part == 0)
                dout[b * 4096 + u * 64 + (ba & 63)] = sv + __ldg(b2v);
            __syncthreads();
        }
    }
}

// ---------------- launch -----------------------------------------------------
extern "C" void kernel_launch(void* const* d_in, const int* in_sizes, int n_in,
                              void* d_out, int out_size) {
    (void)in_sizes; (void)n_in; (void)out_size;
    const float* cg      = (const float*)d_in[0];
    const float* phi1_W1 = (const float*)d_in[1];
    const float* phi1_b1 = (const float*)d_in[2];
    const float* phi1_W2 = (const float*)d_in[3];
    const float* phi1_b2 = (const float*)d_in[4];
    const float* phiK_W1 = (const float*)d_in[5];
    const float* phiK_b1 = (const float*)d_in[6];
    const float* phiK_W2 = (const float*)d_in[7];
    const float* phiK_b2 = (const float*)d_in[8];
    const float* g1_W1   = (const float*)d_in[9];
    const float* g1_b1   = (const float*)d_in[10];
    const float* g1_W2   = (const float*)d_in[11];
    const float* g1_b2   = (const float*)d_in[12];
    const float* gK_W1   = (const float*)d_in[13];
    const float* gK_b1   = (const float*)d_in[14];
    const float* gK_W2   = (const float*)d_in[15];
    const float* gK_b2   = (const float*)d_in[16];
    const float* g5_W1   = (const float*)d_in[17];
    const float* g5_b1   = (const float*)d_in[18];
    const float* g5_W2   = (const float*)d_in[19];
    const float* g5_b2   = (const float*)d_in[20];
    float* out = (float*)d_out;

    auto smem_bytes = [](int KB1, bool fin) {
        int XR = (KB1 * 8 < 32) ? 32 : KB1 * 8;
        int nbuf = fin ? 1 : 2;
        int u32s = KB1 * 1024 + nbuf * 2 * XR * 72 + 160 + (fin ? 64 * 66 : 0);
        return u32s * 4;
    };
    const int SM1 = smem_bytes(1, false);
    const int SM5 = smem_bytes(5, false);
    const int SM8 = smem_bytes(8, false);
    const int SMF = smem_bytes(8, true);

    cudaFuncSetAttribute(layer_kernel<1, 0, false>, cudaFuncAttributeMaxDynamicSharedMemorySize, SM1);
    cudaFuncSetAttribute(layer_kernel<5, 1, false>, cudaFuncAttributeMaxDynamicSharedMemorySize, SM5);
    cudaFuncSetAttribute(layer_kernel<5, 2, false>, cudaFuncAttributeMaxDynamicSharedMemorySize, SM5);
    cudaFuncSetAttribute(layer_kernel<8, 3, false>, cudaFuncAttributeMaxDynamicSharedMemorySize, SM8);
    cudaFuncSetAttribute(layer_kernel<8, 3, true>,  cudaFuncAttributeMaxDynamicSharedMemorySize, SMF);

    prep_kernel<<<19, 256>>>(phi1_W1, phi1_W2, phiK_W1, phiK_W2, g1_W1, g1_W2, gK_W1, gK_W2, g5_W1);
    cgt_kernel<<<128, 256>>>(cg);

    const int G = 296;

    layer_kernel<1, 0, false><<<G, 256, SM1>>>(phi1_b1, phi1_b2, OFF_PHI1_W1F, OFF_PHI1_W2F, nullptr, nullptr);
    asum_kernel<<<1024, 256>>>();
    pP_kernel<<<128, 256>>>(g1_W1, g1_b1, 65, 1);
    layer_kernel<5, 2, false><<<G, 256, SM5>>>(nullptr, g1_b2, OFF_G1_W1F, OFF_G1_W2F, nullptr, nullptr);

    for (int i = 0; i < 4; ++i) {
        layer_kernel<5, 1, false><<<G, 256, SM5>>>(phiK_b1 + i * 64, phiK_b2 + i * 64,
                                                   OFF_PHIK_W1F + i * 5120, OFF_PHIK_W2F + i * 4096,
                                                   nullptr, nullptr);
        asum_kernel<<<1024, 256>>>();
        if (i < 3) {
            pP_kernel<<<128, 256>>>(gK_W1 + i * 8192, gK_b1 + i * 64, 128, 64);
            layer_kernel<8, 3, false><<<G, 256, SM8>>>(nullptr, gK_b2 + i * 64,
                                                       OFF_GK_W1F + i * 8192, OFF_GK_W2F + i * 4096,
                                                       nullptr, nullptr);
        } else {
            pP_kernel<<<128, 256>>>(g5_W1, g5_b1, 128, 64);
            layer_kernel<8, 3, true><<<G, 256, SMF>>>(nullptr, g5_b2,
                                                      OFF_G5_W1F, 0, g5_W2, out);
        }
    }
}

// round 10
// speedup vs baseline: 1.5912x; 1.5912x over previous
#include <cuda_runtime.h>
#include <cuda_fp16.h>
#include <cstdint>

// B=128, U=64, A=64. GEMMs: fp16 mma.sync m16n8k16, SINGLE plane (no hi/lo).
// Intermediates packed fp16: slice = [pair_c(32)][u(64)] u32.
// Persistent CTAs + cp.async double-buffered X; W2 fragments in registers.

#define NBA 8192

__device__ __align__(16) uint32_t g_cgP[NBA * 64];
__device__ __align__(16) uint32_t g_rP[(size_t)NBA * 2048];
__device__ __align__(16) uint32_t g_msgsP[(size_t)NBA * 2048];
__device__ float g_sums[128 * 4096];
__device__ float g_P[128 * 4096];
__device__ __align__(16) uint32_t g_wfrag[48128];

#define OFF_PHI1_W1F 0
#define OFF_PHI1_W2F 512
#define OFF_PHIK_W1F 2560
#define OFF_PHIK_W2F 12800
#define OFF_G1_W1F   20992
#define OFF_G1_W2F   23552
#define OFF_GK_W1F   25600
#define OFF_GK_W2F   37888
#define OFF_G5_W1F   44032

#define CP_ASYNC16(dst, src) asm volatile("cp.async.cg.shared.global [%0], [%1], 16;" :: "r"(dst), "l"(src))
#define CP_COMMIT()          asm volatile("cp.async.commit_group;" ::: "memory")
#define CP_WAIT1()           asm volatile("cp.async.wait_group 1;" ::: "memory")
#define CP_WAIT0()           asm volatile("cp.async.wait_group 0;" ::: "memory")

__device__ __forceinline__ uint32_t packh(float lo, float hi) {
    return (uint32_t)__half_as_ushort(__float2half_rn(lo)) |
           ((uint32_t)__half_as_ushort(__float2half_rn(hi)) << 16);
}
__device__ __forceinline__ void mma16816(float d[4], const uint4& a, uint32_t b0, uint32_t b1) {
    asm volatile("mma.sync.aligned.m16n8k16.row.col.f32.f16.f16.f32 "
                 "{%0,%1,%2,%3}, {%4,%5,%6,%7}, {%8,%9}, {%0,%1,%2,%3};\n"
                 : "+f"(d[0]), "+f"(d[1]), "+f"(d[2]), "+f"(d[3])
                 : "r"(a.x), "r"(a.y), "r"(a.z), "r"(a.w), "r"(b0), "r"(b1));
}

// ---------------- prep: fp16 A-fragments (layout verified R4-R8) -------------
__global__ void prep_kernel(const float* __restrict__ phi1W1, const float* __restrict__ phi1W2,
                            const float* __restrict__ phiKW1, const float* __restrict__ phiKW2,
                            const float* __restrict__ g1W1,   const float* __restrict__ g1W2,
                            const float* __restrict__ gKW1,   const float* __restrict__ gKW2,
                            const float* __restrict__ g5W1) {
    const int id = blockIdx.x;
    const float* src; int off, KB, type;
    if (id == 0)       { src = phi1W1;              off = OFF_PHI1_W1F;            KB = 1; type = 3; }
    else if (id == 1)  { src = phi1W2;              off = OFF_PHI1_W2F;            KB = 4; type = 0; }
    else if (id < 6)   { int i = id - 2;  src = phiKW1 + i * 64 * 65;  off = OFF_PHIK_W1F + i * 2560; KB = 5; type = 1; }
    else if (id < 10)  { int i = id - 6;  src = phiKW2 + i * 4096;     off = OFF_PHIK_W2F + i * 2048; KB = 4; type = 0; }
    else if (id == 10) { src = g1W1;                off = OFF_G1_W1F;              KB = 5; type = 4; }
    else if (id == 11) { src = g1W2;                off = OFF_G1_W2F;              KB = 4; type = 0; }
    else if (id < 15)  { int i = id - 12; src = gKW1 + i * 64 * 128;   off = OFF_GK_W1F + i * 4096;   KB = 8; type = 5; }
    else if (id < 18)  { int i = id - 15; src = gKW2 + i * 4096;       off = OFF_GK_W2F + i * 2048;   KB = 4; type = 0; }
    else               { src = g5W1;                off = OFF_G5_W1F;              KB = 8; type = 5; }

    const float ninv = -1.0f / 63.0f;
    const int total = KB * 512;
    for (int e = threadIdx.x; e < total; e += blockDim.x) {
        int strip = e / (KB * 128);
        int rem   = e % (KB * 128);
        int kt = rem / 128;
        int r3 = rem & 127;
        int lane = r3 >> 2, j = r3 & 3;
        int o  = strip * 16 + (lane >> 2) + 8 * (j & 1);
        int k0 = kt * 16 + (lane & 3) * 2 + 8 * (j >> 1);
        float w0, w1;
        if (type == 0)      { w0 = src[o * 64 + k0];  w1 = src[o * 64 + k0 + 1]; }
        else if (type == 5) { w0 = src[o * 128 + k0]; w1 = src[o * 128 + k0 + 1];
                              if (k0 >= 64) { w0 *= ninv; w1 *= ninv; } }
        else if (type == 1 || type == 4) {
            auto fetch = [&](int c) -> float {
                if (c < 64) { float v = src[o * 65 + 1 + c]; return (type == 4) ? v * ninv : v; }
                if (c == 64) return src[o * 65];
                return 0.0f;
            };
            w0 = fetch(k0); w1 = fetch(k0 + 1);
        } else {
            w0 = (k0 == 0) ? (src[o * 2] + src[o * 2 + 1]) : 0.0f;
            w1 = 0.0f;
        }
        g_wfrag[off + e] = packh(w0, w1);
    }
}

// ---------------- cg transpose + pack ----------------------------------------
__global__ void cgt_kernel(const float* __restrict__ cg) {
    const int b = blockIdx.x;
    for (int j = threadIdx.x; j < 4096; j += 256) {
        int a = j >> 6, u = j & 63;
        float v = cg[b * 4096 + u * 64 + a];
        g_cgP[(b * 64 + a) * 64 + u] = packh(v, 0.0f);
    }
}

// ---------------- sum over a of packed msgs -----------------------------------
__global__ void asum_kernel() {
    const int b = blockIdx.x >> 3;
    const int e = (blockIdx.x & 7) * 256 + threadIdx.x;   // pair*64+u
    const uint32_t* p0 = g_msgsP + (size_t)b * 131072 + e;
    float s0 = 0.f, s1 = 0.f;
#pragma unroll 8
    for (int a = 0; a < 64; ++a) {
        uint32_t h = p0[(size_t)a * 2048];
        __half2 hv = *reinterpret_cast<const __half2*>(&h);
        float2 f = __half22float2(hv);
        s0 += f.x; s1 += f.y;
    }
    int pr = e >> 6, u = e & 63;
    g_sums[b * 4096 + (2 * pr) * 64 + u]     = s0;
    g_sums[b * 4096 + (2 * pr + 1) * 64 + u] = s1;
}

// ---------------- per-b precompute: P = bias1 + (Wagg/63)*S -------------------
__global__ void pP_kernel(const float* __restrict__ Wsrc, const float* __restrict__ b1,
                          int CW, int cOff) {
    __shared__ float sWT[64 * 65];
    __shared__ float sS2[4096];
    const int b = blockIdx.x, t = threadIdx.x;
    for (int idx = t; idx < 4096; idx += 256) {
        int o = idx >> 6, c = idx & 63;
        sWT[c * 65 + o] = Wsrc[o * CW + cOff + c] * (1.0f / 63.0f);
        sS2[idx] = g_sums[b * 4096 + idx];
    }
    __syncthreads();
    const int o = t & 63, ublk = t >> 6;
    float acc[16];
    float bv = __ldg(b1 + o);
#pragma unroll
    for (int i = 0; i < 16; ++i) acc[i] = bv;
    const float4* S4 = (const float4*)sS2;
#pragma unroll 4
    for (int c = 0; c < 64; ++c) {
        float w = sWT[c * 65 + o];
#pragma unroll
        for (int i = 0; i < 4; ++i) {
            float4 s = S4[c * 16 + ublk * 4 + i];
            acc[i * 4 + 0] += w * s.x; acc[i * 4 + 1] += w * s.y;
            acc[i * 4 + 2] += w * s.z; acc[i * 4 + 3] += w * s.w;
        }
    }
    float4* P4 = (float4*)(g_P + b * 4096 + o * 64 + ublk * 16);
#pragma unroll
    for (int i = 0; i < 4; ++i)
        P4[i] = make_float4(acc[i * 4], acc[i * 4 + 1], acc[i * 4 + 2], acc[i * 4 + 3]);
}

// ---------------- cp.async prefetch of one slice into an X buffer -------------
template<int MODE, int XR>
__device__ __forceinline__ void prefetch_slice(uint32_t dstH, int ba, int t) {
    const uint32_t* rP = g_rP + (size_t)ba * 2048;
    const uint32_t* mP = g_msgsP + (size_t)ba * 2048;
    const uint32_t* ch = g_cgP + ba * 64;
    constexpr int NR = (MODE == 0) ? 1 : (MODE == 3) ? 64 : 33;
    for (int cc = t; cc < NR * 16; cc += 256) {
        int row = cc >> 4, c4 = (cc & 15) * 4;
        const uint32_t* src;
        if (MODE == 0) {
            src = ch + c4;
        } else if (MODE == 3) {
            src = (row < 32) ? (rP + row * 64 + c4) : (mP + (row - 32) * 64 + c4);
        } else {
            const uint32_t* base = (MODE == 1) ? rP : mP;
            src = (row < 32) ? (base + row * 64 + c4) : (ch + c4);   // row == 32 -> cg
        }
        CP_ASYNC16(dstH + (uint32_t)(row * 72 + c4) * 4u, src);
    }
}

// ---------------- layer kernel (persistent, double-buffered) ------------------
// MODE: 0 phi1, 1 phiK, 2 gamma1, 3 gammaK/gamma5
template<int KB1, int MODE, bool FINAL>
__global__ void __launch_bounds__(256, 2) layer_kernel(const float* __restrict__ b1v,
                                                       const float* __restrict__ b2v,
                                                       int w1off, int w2off,
                                                       const float* __restrict__ w2raw,
                                                       float* __restrict__ dout) {
    constexpr bool RELU2 = (MODE >= 2);
    constexpr bool DB = !FINAL;
    constexpr int XR = (KB1 * 8 < 32) ? 32 : KB1 * 8;
    constexpr int BUFU = XR * 72;
    extern __shared__ uint32_t sm[];
    uint32_t* sW1f = sm;                                  // KB1*512
    uint32_t* sX   = sW1f + KB1 * 512;                    // (DB?2:1)*BUFU
    float*    sS   = (float*)(sX + (DB ? 2 : 1) * BUFU);  // 160
    float*    sH   = sS + 160;                            // 64*66 (FINAL only)

    const int t = threadIdx.x;
    const int warp = t >> 5, lane = t & 31, q = lane & 3, g = lane >> 2;
    const int s = warp >> 1, h2 = warp & 1;
    const int ub = h2 * 32;
    const int o_r = s * 16 + g, o_r8 = o_r + 8;
    const bool geven = ((g & 1) == 0);
    const float inv = 1.0f / 63.0f;

    uint32_t smbase;
    asm("{ .reg .u64 tmp; cvta.to.shared.u64 tmp, %1; cvt.u32.u64 %0, tmp; }"
        : "=r"(smbase) : "l"(sm));
    const uint32_t xbase = smbase + (uint32_t)(KB1 * 512) * 4u;

    // W1 to smem; W2 fragments to registers
    {
        const uint4* gw1 = (const uint4*)(g_wfrag + w1off);
        uint4* d1 = (uint4*)sW1f;
        for (int i = t; i < KB1 * 128; i += 256) d1[i] = gw1[i];
    }
    uint4 W2r[4];
    if (!FINAL) {
        const uint4* gw2 = (const uint4*)(g_wfrag + w2off);
#pragma unroll
        for (int kt = 0; kt < 4; ++kt) W2r[kt] = gw2[s * 128 + kt * 32 + lane];
    }
    float bA1 = 0.f, bB1 = 0.f, bA2 = 0.f, bB2 = 0.f;
    if (MODE < 2) { bA1 = __ldg(b1v + o_r); bB1 = __ldg(b1v + o_r8); }
    if (!FINAL)   { bA2 = __ldg(b2v + o_r); bB2 = __ldg(b2v + o_r8); }

    for (int i = t; i < (DB ? 2 : 1) * BUFU; i += 256) sX[i] = 0;
    __syncthreads();

    const int stride = gridDim.x;
    int o = 0;
    if (DB) {
        if ((int)blockIdx.x < NBA) prefetch_slice<MODE, XR>(xbase, blockIdx.x, t);
        CP_COMMIT();
    }

    for (int ba = blockIdx.x; ba < NBA; ba += stride) {
        const int b = ba >> 6;
        if (DB) {
            int nxt = ba + stride;
            if (nxt < NBA) prefetch_slice<MODE, XR>(xbase + (uint32_t)((o ^ 1) * BUFU) * 4u, nxt, t);
            CP_COMMIT();
            CP_WAIT1();
        } else {
            prefetch_slice<MODE, XR>(xbase, ba, t);
            CP_COMMIT();
            CP_WAIT0();
        }
        __syncthreads();

        uint32_t* bH = sX + o * BUFU;

        float2 pa[4], pb[4];
        if (MODE >= 2) {
            const float* Pb = g_P + b * 4096;
#pragma unroll
            for (int nt = 0; nt < 4; ++nt) {
                int u0 = ub + nt * 8 + q * 2;
                pa[nt] = __ldg((const float2*)(Pb + o_r * 64 + u0));
                pb[nt] = __ldg((const float2*)(Pb + o_r8 * 64 + u0));
            }
        }

        // ---- conv1 ----
        float acc[4][4];
#pragma unroll
        for (int nt = 0; nt < 4; ++nt)
#pragma unroll
            for (int j = 0; j < 4; ++j) acc[nt][j] = 0.f;
        {
            const uint4* A1 = (const uint4*)sW1f + s * (KB1 * 32);
#pragma unroll
            for (int kt = 0; kt < KB1; ++kt) {
                uint4 Ah = A1[kt * 32 + lane];
                const uint32_t* xh0 = bH + (kt * 8 + q) * 72 + ub + g;
                const uint32_t* xh1 = bH + (kt * 8 + 4 + q) * 72 + ub + g;
                uint32_t bh0[4], bh1[4];
#pragma unroll
                for (int nt = 0; nt < 4; ++nt) { bh0[nt] = xh0[nt * 8]; bh1[nt] = xh1[nt * 8]; }
#pragma unroll
                for (int nt = 0; nt < 4; ++nt) mma16816(acc[nt], Ah, bh0[nt], bh1[nt]);
            }
        }
        if (MODE >= 2) {
#pragma unroll
            for (int nt = 0; nt < 4; ++nt) {
                acc[nt][0] += pa[nt].x; acc[nt][1] += pa[nt].y;
                acc[nt][2] += pb[nt].x; acc[nt][3] += pb[nt].y;
            }
        } else {
#pragma unroll
            for (int nt = 0; nt < 4; ++nt) {
                acc[nt][0] += bA1; acc[nt][1] += bA1;
                acc[nt][2] += bB1; acc[nt][3] += bB1;
            }
        }
#pragma unroll
        for (int nt = 0; nt < 4; ++nt)
#pragma unroll
            for (int j = 0; j < 4; ++j) acc[nt][j] = fmaxf(acc[nt][j], 0.0f);
        {
            float sA = 0.f, sB = 0.f;
#pragma unroll
            for (int nt = 0; nt < 4; ++nt) { sA += acc[nt][0] + acc[nt][1]; sB += acc[nt][2] + acc[nt][3]; }
            sA += __shfl_xor_sync(0xffffffffu, sA, 1); sA += __shfl_xor_sync(0xffffffffu, sA, 2);
            sB += __shfl_xor_sync(0xffffffffu, sB, 1); sB += __shfl_xor_sync(0xffffffffu, sB, 2);
            if (q == 0) { sS[h2 * 80 + o_r] = sA; sS[h2 * 80 + o_r8] = sB; }
        }
        __syncthreads();
        float SA = sS[o_r] + sS[80 + o_r];
        float SB = sS[o_r8] + sS[80 + o_r8];

        if (!FINAL) {
            // post + pair-pack into current buffer rows 0..31 (fp16 single plane)
#pragma unroll
            for (int nt = 0; nt < 4; ++nt) {
                float t0, t1, t2, t3;
                if (s >= 2) {
                    t0 = (SA - acc[nt][0]) * inv; t1 = (SA - acc[nt][1]) * inv;
                    t2 = (SB - acc[nt][2]) * inv; t3 = (SB - acc[nt][3]) * inv;
                } else { t0 = acc[nt][0]; t1 = acc[nt][1]; t2 = acc[nt][2]; t3 = acc[nt][3]; }
                float p0 = __shfl_xor_sync(0xffffffffu, t0, 4);
                float p1 = __shfl_xor_sync(0xffffffffu, t1, 4);
                float p2 = __shfl_xor_sync(0xffffffffu, t2, 4);
                float p3 = __shfl_xor_sync(0xffffffffu, t3, 4);
                float v0a, v0b, v1a, v1b; int c2;
                if (geven) { c2 = (s * 16 + g) >> 1;          v0a = t0; v0b = p0; v1a = t1; v1b = p1; }
                else       { c2 = (s * 16 + 8 + g - 1) >> 1;  v0a = p2; v0b = t2; v1a = p3; v1b = t3; }
                int u0 = ub + nt * 8 + q * 2;
                bH[c2 * 72 + u0]     = packh(v0a, v0b);
                bH[c2 * 72 + u0 + 1] = packh(v1a, v1b);
            }
            __syncthreads();

            // ---- conv2 (KB=4, W2 in registers) ----
            float a2[4][4];
#pragma unroll
            for (int nt = 0; nt < 4; ++nt)
#pragma unroll
                for (int j = 0; j < 4; ++j) a2[nt][j] = 0.f;
#pragma unroll
            for (int kt = 0; kt < 4; ++kt) {
                const uint32_t* xh0 = bH + (kt * 8 + q) * 72 + ub + g;
                const uint32_t* xh1 = bH + (kt * 8 + 4 + q) * 72 + ub + g;
                uint32_t bh0[4], bh1[4];
#pragma unroll
                for (int nt = 0; nt < 4; ++nt) { bh0[nt] = xh0[nt * 8]; bh1[nt] = xh1[nt * 8]; }
#pragma unroll
                for (int nt = 0; nt < 4; ++nt) mma16816(a2[nt], W2r[kt], bh0[nt], bh1[nt]);
            }
#pragma unroll
            for (int nt = 0; nt < 4; ++nt) {
                a2[nt][0] += bA2; a2[nt][1] += bA2;
                a2[nt][2] += bB2; a2[nt][3] += bB2;
            }
            if (RELU2) {
#pragma unroll
                for (int nt = 0; nt < 4; ++nt)
#pragma unroll
                    for (int j = 0; j < 4; ++j) a2[nt][j] = fmaxf(a2[nt][j], 0.0f);
            }
            float s2A = 0.f, s2B = 0.f;
#pragma unroll
            for (int nt = 0; nt < 4; ++nt) { s2A += a2[nt][0] + a2[nt][1]; s2B += a2[nt][2] + a2[nt][3]; }
            s2A += __shfl_xor_sync(0xffffffffu, s2A, 1); s2A += __shfl_xor_sync(0xffffffffu, s2A, 2);
            s2B += __shfl_xor_sync(0xffffffffu, s2B, 1); s2B += __shfl_xor_sync(0xffffffffu, s2B, 2);
            if (q == 0) { sS[h2 * 80 + o_r] = s2A; sS[h2 * 80 + o_r8] = s2B; }
            __syncthreads();
            float S2A = sS[o_r] + sS[80 + o_r];
            float S2B = sS[o_r8] + sS[80 + o_r8];

            uint32_t* gout = (RELU2 ? g_rP : g_msgsP) + (size_t)ba * 2048;
#pragma unroll
            for (int nt = 0; nt < 4; ++nt) {
                float t0, t1, t2, t3;
                if (s >= 2) {
                    t0 = (S2A - a2[nt][0]) * inv; t1 = (S2A - a2[nt][1]) * inv;
                    t2 = (S2B - a2[nt][2]) * inv; t3 = (S2B - a2[nt][3]) * inv;
                } else { t0 = a2[nt][0]; t1 = a2[nt][1]; t2 = a2[nt][2]; t3 = a2[nt][3]; }
                float p0 = __shfl_xor_sync(0xffffffffu, t0, 4);
                float p1 = __shfl_xor_sync(0xffffffffu, t1, 4);
                float p2 = __shfl_xor_sync(0xffffffffu, t2, 4);
                float p3 = __shfl_xor_sync(0xffffffffu, t3, 4);
                float v0a, v0b, v1a, v1b; int c2;
                if (geven) { c2 = (s * 16 + g) >> 1;          v0a = t0; v0b = p0; v1a = t1; v1b = p1; }
                else       { c2 = (s * 16 + 8 + g - 1) >> 1;  v0a = p2; v0b = t2; v1a = p3; v1b = t3; }
                int u0 = ub + nt * 8 + q * 2;
                uint2 vh; vh.x = packh(v0a, v0b); vh.y = packh(v1a, v1b);
                *(uint2*)(gout + c2 * 64 + u0) = vh;
            }
            o ^= 1;
        } else {
            // FINAL: post-transformed H to sH, then 1x64 GEMV
#pragma unroll
            for (int nt = 0; nt < 4; ++nt) {
                int u0 = ub + nt * 8 + q * 2;
                float2 vA, vB;
                if (s >= 2) {
                    vA.x = (SA - acc[nt][0]) * inv; vA.y = (SA - acc[nt][1]) * inv;
                    vB.x = (SB - acc[nt][2]) * inv; vB.y = (SB - acc[nt][3]) * inv;
                } else { vA.x = acc[nt][0]; vA.y = acc[nt][1]; vB.x = acc[nt][2]; vB.y = acc[nt][3]; }
                *(float2*)(sH + o_r * 66 + u0)  = vA;
                *(float2*)(sH + o_r8 * 66 + u0) = vB;
            }
            __syncthreads();
            const int u = t >> 2, part = t & 3;
            float sv = 0.0f;
            const int c0 = part * 16;
#pragma unroll
            for (int c = c0; c < c0 + 16; ++c)
                sv = fmaf(__ldg(w2raw + c), sH[c * 66 + u], sv);
            sv += __shfl_xor_sync(0xffffffffu, sv, 1);
            sv += __shfl_xor_sync(0xffffffffu, sv, 2);
            if (part == 0)
                dout[b * 4096 + u * 64 + (ba & 63)] = sv + __ldg(b2v);
            __syncthreads();
        }
    }
}

// ---------------- launch -----------------------------------------------------
extern "C" void kernel_launch(void* const* d_in, const int* in_sizes, int n_in,
                              void* d_out, int out_size) {
    (void)in_sizes; (void)n_in; (void)out_size;
    const float* cg      = (const float*)d_in[0];
    const float* phi1_W1 = (const float*)d_in[1];
    const float* phi1_b1 = (const float*)d_in[2];
    const float* phi1_W2 = (const float*)d_in[3];
    const float* phi1_b2 = (const float*)d_in[4];
    const float* phiK_W1 = (const float*)d_in[5];
    const float* phiK_b1 = (const float*)d_in[6];
    const float* phiK_W2 = (const float*)d_in[7];
    const float* phiK_b2 = (const float*)d_in[8];
    const float* g1_W1   = (const float*)d_in[9];
    const float* g1_b1   = (const float*)d_in[10];
    const float* g1_W2   = (const float*)d_in[11];
    const float* g1_b2   = (const float*)d_in[12];
    const float* gK_W1   = (const float*)d_in[13];
    const float* gK_b1   = (const float*)d_in[14];
    const float* gK_W2   = (const float*)d_in[15];
    const float* gK_b2   = (const float*)d_in[16];
    const float* g5_W1   = (const float*)d_in[17];
    const float* g5_b1   = (const float*)d_in[18];
    const float* g5_W2   = (const float*)d_in[19];
    const float* g5_b2   = (const float*)d_in[20];
    float* out = (float*)d_out;

    auto smem_bytes = [](int KB1, bool fin) {
        int XR = (KB1 * 8 < 32) ? 32 : KB1 * 8;
        int nbuf = fin ? 1 : 2;
        int u32s = KB1 * 512 + nbuf * XR * 72 + 160 + (fin ? 64 * 66 : 0);
        return u32s * 4;
    };
    const int SM1 = smem_bytes(1, false);
    const int SM5 = smem_bytes(5, false);
    const int SM8 = smem_bytes(8, false);
    const int SMF = smem_bytes(8, true);

    cudaFuncSetAttribute(layer_kernel<1, 0, false>, cudaFuncAttributeMaxDynamicSharedMemorySize, SM1);
    cudaFuncSetAttribute(layer_kernel<5, 1, false>, cudaFuncAttributeMaxDynamicSharedMemorySize, SM5);
    cudaFuncSetAttribute(layer_kernel<5, 2, false>, cudaFuncAttributeMaxDynamicSharedMemorySize, SM5);
    cudaFuncSetAttribute(layer_kernel<8, 3, false>, cudaFuncAttributeMaxDynamicSharedMemorySize, SM8);
    cudaFuncSetAttribute(layer_kernel<8, 3, true>,  cudaFuncAttributeMaxDynamicSharedMemorySize, SMF);

    prep_kernel<<<19, 256>>>(phi1_W1, phi1_W2, phiK_W1, phiK_W2, g1_W1, g1_W2, gK_W1, gK_W2, g5_W1);
    cgt_kernel<<<128, 256>>>(cg);

    const int G = 296;

    layer_kernel<1, 0, false><<<G, 256, SM1>>>(phi1_b1, phi1_b2, OFF_PHI1_W1F, OFF_PHI1_W2F, nullptr, nullptr);
    asum_kernel<<<1024, 256>>>();
    pP_kernel<<<128, 256>>>(g1_W1, g1_b1, 65, 1);
    layer_kernel<5, 2, false><<<G, 256, SM5>>>(nullptr, g1_b2, OFF_G1_W1F, OFF_G1_W2F, nullptr, nullptr);

    for (int i = 0; i < 4; ++i) {
        layer_kernel<5, 1, false><<<G, 256, SM5>>>(phiK_b1 + i * 64, phiK_b2 + i * 64,
                                                   OFF_PHIK_W1F + i * 2560, OFF_PHIK_W2F + i * 2048,
                                                   nullptr, nullptr);
        asum_kernel<<<1024, 256>>>();
        if (i < 3) {
            pP_kernel<<<128, 256>>>(gK_W1 + i * 8192, gK_b1 + i * 64, 128, 64);
            layer_kernel<8, 3, false><<<G, 256, SM8>>>(nullptr, gK_b2 + i * 64,
                                                       OFF_GK_W1F + i * 4096, OFF_GK_W2F + i * 2048,
                                                       nullptr, nullptr);
        } else {
            pP_kernel<<<128, 256>>>(g5_W1, g5_b1, 128, 64);
            layer_kernel<8, 3, true><<<G, 256, SMF>>>(nullptr, g5_b2,
                                                      OFF_G5_W1F, 0, g5_W2, out);
        }
    }
}

// round 11
// speedup vs baseline: 1.9226x; 1.2083x over previous
#include <cuda_runtime.h>
#include <cuda_fp16.h>
#include <cstdint>

// B=128, U=64, A=64. GEMMs: fp16 mma.sync m16n8k16 single-plane.
// CTA = 2 independent 128-thread halves, each a persistent slice stream.
// Warp owns 16 rows x 64 u (nt=8) -> colsum fully in-register.

#define NBA 8192

__device__ __align__(16) uint32_t g_cgP[NBA * 64];
__device__ __align__(16) uint32_t g_rP[(size_t)NBA * 2048];
__device__ __align__(16) uint32_t g_msgsP[(size_t)NBA * 2048];
__device__ float g_sums[128 * 4096];
__device__ float g_P[128 * 4096];
__device__ __align__(16) uint32_t g_wfrag[48128];

#define OFF_PHI1_W1F 0
#define OFF_PHI1_W2F 512
#define OFF_PHIK_W1F 2560
#define OFF_PHIK_W2F 12800
#define OFF_G1_W1F   20992
#define OFF_G1_W2F   23552
#define OFF_GK_W1F   25600
#define OFF_GK_W2F   37888
#define OFF_G5_W1F   44032

#define CP_ASYNC16(dst, src) asm volatile("cp.async.cg.shared.global [%0], [%1], 16;" :: "r"(dst), "l"(src))
#define CP_COMMIT()          asm volatile("cp.async.commit_group;" ::: "memory")
#define CP_WAIT1()           asm volatile("cp.async.wait_group 1;" ::: "memory")
#define BARH(id)             asm volatile("bar.sync %0, 128;" :: "r"(id) : "memory")

__device__ __forceinline__ uint32_t packh(float lo, float hi) {
    return (uint32_t)__half_as_ushort(__float2half_rn(lo)) |
           ((uint32_t)__half_as_ushort(__float2half_rn(hi)) << 16);
}
__device__ __forceinline__ void mma16816(float d[4], const uint4& a, uint32_t b0, uint32_t b1) {
    asm volatile("mma.sync.aligned.m16n8k16.row.col.f32.f16.f16.f32 "
                 "{%0,%1,%2,%3}, {%4,%5,%6,%7}, {%8,%9}, {%0,%1,%2,%3};\n"
                 : "+f"(d[0]), "+f"(d[1]), "+f"(d[2]), "+f"(d[3])
                 : "r"(a.x), "r"(a.y), "r"(a.z), "r"(a.w), "r"(b0), "r"(b1));
}

// ---------------- prep: fp16 A-fragments (verified R10) ----------------------
__global__ void prep_kernel(const float* __restrict__ phi1W1, const float* __restrict__ phi1W2,
                            const float* __restrict__ phiKW1, const float* __restrict__ phiKW2,
                            const float* __restrict__ g1W1,   const float* __restrict__ g1W2,
                            const float* __restrict__ gKW1,   const float* __restrict__ gKW2,
                            const float* __restrict__ g5W1) {
    const int id = blockIdx.x;
    const float* src; int off, KB, type;
    if (id == 0)       { src = phi1W1;              off = OFF_PHI1_W1F;            KB = 1; type = 3; }
    else if (id == 1)  { src = phi1W2;              off = OFF_PHI1_W2F;            KB = 4; type = 0; }
    else if (id < 6)   { int i = id - 2;  src = phiKW1 + i * 64 * 65;  off = OFF_PHIK_W1F + i * 2560; KB = 5; type = 1; }
    else if (id < 10)  { int i = id - 6;  src = phiKW2 + i * 4096;     off = OFF_PHIK_W2F + i * 2048; KB = 4; type = 0; }
    else if (id == 10) { src = g1W1;                off = OFF_G1_W1F;              KB = 5; type = 4; }
    else if (id == 11) { src = g1W2;                off = OFF_G1_W2F;              KB = 4; type = 0; }
    else if (id < 15)  { int i = id - 12; src = gKW1 + i * 64 * 128;   off = OFF_GK_W1F + i * 4096;   KB = 8; type = 5; }
    else if (id < 18)  { int i = id - 15; src = gKW2 + i * 4096;       off = OFF_GK_W2F + i * 2048;   KB = 4; type = 0; }
    else               { src = g5W1;                off = OFF_G5_W1F;              KB = 8; type = 5; }

    const float ninv = -1.0f / 63.0f;
    const int total = KB * 512;
    for (int e = threadIdx.x; e < total; e += blockDim.x) {
        int strip = e / (KB * 128);
        int rem   = e % (KB * 128);
        int kt = rem / 128;
        int r3 = rem & 127;
        int lane = r3 >> 2, j = r3 & 3;
        int o  = strip * 16 + (lane >> 2) + 8 * (j & 1);
        int k0 = kt * 16 + (lane & 3) * 2 + 8 * (j >> 1);
        float w0, w1;
        if (type == 0)      { w0 = src[o * 64 + k0];  w1 = src[o * 64 + k0 + 1]; }
        else if (type == 5) { w0 = src[o * 128 + k0]; w1 = src[o * 128 + k0 + 1];
                              if (k0 >= 64) { w0 *= ninv; w1 *= ninv; } }
        else if (type == 1 || type == 4) {
            auto fetch = [&](int c) -> float {
                if (c < 64) { float v = src[o * 65 + 1 + c]; return (type == 4) ? v * ninv : v; }
                if (c == 64) return src[o * 65];
                return 0.0f;
            };
            w0 = fetch(k0); w1 = fetch(k0 + 1);
        } else {
            w0 = (k0 == 0) ? (src[o * 2] + src[o * 2 + 1]) : 0.0f;
            w1 = 0.0f;
        }
        g_wfrag[off + e] = packh(w0, w1);
    }
}

__global__ void cgt_kernel(const float* __restrict__ cg) {
    const int b = blockIdx.x;
    for (int j = threadIdx.x; j < 4096; j += 256) {
        int a = j >> 6, u = j & 63;
        g_cgP[(b * 64 + a) * 64 + u] = packh(cg[b * 4096 + u * 64 + a], 0.0f);
    }
}

__global__ void asum_kernel() {
    const int b = blockIdx.x >> 3;
    const int e = (blockIdx.x & 7) * 256 + threadIdx.x;
    const uint32_t* p0 = g_msgsP + (size_t)b * 131072 + e;
    float s0 = 0.f, s1 = 0.f;
#pragma unroll 8
    for (int a = 0; a < 64; ++a) {
        uint32_t h = p0[(size_t)a * 2048];
        __half2 hv = *reinterpret_cast<const __half2*>(&h);
        float2 f = __half22float2(hv);
        s0 += f.x; s1 += f.y;
    }
    int pr = e >> 6, u = e & 63;
    g_sums[b * 4096 + (2 * pr) * 64 + u]     = s0;
    g_sums[b * 4096 + (2 * pr + 1) * 64 + u] = s1;
}

__global__ void pP_kernel(const float* __restrict__ Wsrc, const float* __restrict__ b1,
                          int CW, int cOff) {
    __shared__ float sWT[64 * 65];
    __shared__ float sS2[4096];
    const int b = blockIdx.x, t = threadIdx.x;
    for (int idx = t; idx < 4096; idx += 256) {
        int o = idx >> 6, c = idx & 63;
        sWT[c * 65 + o] = Wsrc[o * CW + cOff + c] * (1.0f / 63.0f);
        sS2[idx] = g_sums[b * 4096 + idx];
    }
    __syncthreads();
    const int o = t & 63, ublk = t >> 6;
    float acc[16];
    float bv = __ldg(b1 + o);
#pragma unroll
    for (int i = 0; i < 16; ++i) acc[i] = bv;
    const float4* S4 = (const float4*)sS2;
#pragma unroll 4
    for (int c = 0; c < 64; ++c) {
        float w = sWT[c * 65 + o];
#pragma unroll
        for (int i = 0; i < 4; ++i) {
            float4 s = S4[c * 16 + ublk * 4 + i];
            acc[i * 4 + 0] += w * s.x; acc[i * 4 + 1] += w * s.y;
            acc[i * 4 + 2] += w * s.z; acc[i * 4 + 3] += w * s.w;
        }
    }
    float4* P4 = (float4*)(g_P + b * 4096 + o * 64 + ublk * 16);
#pragma unroll
    for (int i = 0; i < 4; ++i)
        P4[i] = make_float4(acc[i * 4], acc[i * 4 + 1], acc[i * 4 + 2], acc[i * 4 + 3]);
}

// ---------------- cp.async prefetch (128-thread half) -------------------------
template<int MODE, int XR>
__device__ __forceinline__ void prefetch_slice(uint32_t dstH, int ba, int t2) {
    const uint32_t* rP = g_rP + (size_t)ba * 2048;
    const uint32_t* mP = g_msgsP + (size_t)ba * 2048;
    const uint32_t* ch = g_cgP + ba * 64;
    constexpr int NR = (MODE == 0) ? 1 : (MODE == 3) ? 64 : 33;
    for (int cc = t2; cc < NR * 16; cc += 128) {
        int row = cc >> 4, c4 = (cc & 15) * 4;
        const uint32_t* src;
        if (MODE == 0) src = ch + c4;
        else if (MODE == 3) src = (row < 32) ? (rP + row * 64 + c4) : (mP + (row - 32) * 64 + c4);
        else {
            const uint32_t* base = (MODE == 1) ? rP : mP;
            src = (row < 32) ? (base + row * 64 + c4) : (ch + c4);
        }
        CP_ASYNC16(dstH + (uint32_t)(row * 72 + c4) * 4u, src);
    }
}

// ---------------- layer kernel: 2 independent halves --------------------------
// MODE: 0 phi1, 1 phiK, 2 gamma1, 3 gammaK/gamma5
template<int KB1, int MODE, bool FINAL>
__global__ void __launch_bounds__(256, 2) layer_kernel(const float* __restrict__ b1v,
                                                       const float* __restrict__ b2v,
                                                       int w1off, int w2off,
                                                       const float* __restrict__ w2raw,
                                                       float* __restrict__ dout) {
    constexpr bool RELU2 = (MODE >= 2);
    constexpr int XR = (KB1 * 8 < 32) ? 32 : KB1 * 8;
    constexpr int BUFU = XR * 72;
    extern __shared__ uint32_t sm[];
    uint32_t* sW1f = sm;                       // KB1*512
    uint32_t* sX   = sW1f + KB1 * 512;         // 4*BUFU : [half*2 + o]
    float*    sRed = (float*)(sX + 4 * BUFU);  // 512 (FINAL only)

    const int t = threadIdx.x;
    const int warp = t >> 5, lane = t & 31, q = lane & 3, g = lane >> 2;
    const int half = warp >> 2, wl = warp & 3;
    const int t2 = t & 127;
    const int o_r = wl * 16 + g, o_r8 = o_r + 8;
    const bool geven = ((g & 1) == 0);
    const float inv = 1.0f / 63.0f;
    const int barid = 1 + half;

    uint32_t smbase;
    asm("{ .reg .u64 tmp; cvta.to.shared.u64 tmp, %1; cvt.u32.u64 %0, tmp; }"
        : "=r"(smbase) : "l"(sm));
    const uint32_t xbase = smbase + (uint32_t)(KB1 * 512) * 4u;

    {
        const uint4* gw1 = (const uint4*)(g_wfrag + w1off);
        uint4* d1 = (uint4*)sW1f;
        for (int i = t; i < KB1 * 128; i += 256) d1[i] = gw1[i];
    }
    uint4 W2r[4];
    if (!FINAL) {
        const uint4* gw2 = (const uint4*)(g_wfrag + w2off);
#pragma unroll
        for (int kt = 0; kt < 4; ++kt) W2r[kt] = gw2[wl * 128 + kt * 32 + lane];
    }
    float bA1 = 0.f, bB1 = 0.f, bA2 = 0.f, bB2 = 0.f, w2a = 0.f, w2b = 0.f, bF = 0.f;
    if (MODE < 2) { bA1 = __ldg(b1v + o_r); bB1 = __ldg(b1v + o_r8); }
    if (!FINAL)   { bA2 = __ldg(b2v + o_r); bB2 = __ldg(b2v + o_r8); }
    if (FINAL)    { w2a = __ldg(w2raw + o_r); w2b = __ldg(w2raw + o_r8); bF = __ldg(b2v); }

    for (int i = t; i < 4 * BUFU; i += 256) sX[i] = 0;
    __syncthreads();

    const int stride2 = gridDim.x * 2;
    const int stream = blockIdx.x * 2 + half;
    int o = 0;
    prefetch_slice<MODE, XR>(xbase + (uint32_t)((half * 2) * BUFU) * 4u, stream, t2);
    CP_COMMIT();

    for (int ba = stream; ba < NBA; ba += stride2) {
        const int b = ba >> 6;
        int nxt = ba + stride2;
        if (nxt < NBA)
            prefetch_slice<MODE, XR>(xbase + (uint32_t)((half * 2 + (o ^ 1)) * BUFU) * 4u, nxt, t2);
        CP_COMMIT();
        CP_WAIT1();
        BARH(barid);

        uint32_t* bH = sX + (half * 2 + o) * BUFU;

        // ---- conv1 ----
        float acc[8][4];
#pragma unroll
        for (int nt = 0; nt < 8; ++nt)
#pragma unroll
            for (int j = 0; j < 4; ++j) acc[nt][j] = 0.f;
        {
            const uint4* A1 = (const uint4*)sW1f + wl * (KB1 * 32);
#pragma unroll
            for (int kt = 0; kt < KB1; ++kt) {
                uint4 Ah = A1[kt * 32 + lane];
                const uint32_t* xh0 = bH + (kt * 8 + q) * 72 + g;
                const uint32_t* xh1 = bH + (kt * 8 + 4 + q) * 72 + g;
                uint32_t bh0[8], bh1[8];
#pragma unroll
                for (int nt = 0; nt < 8; ++nt) { bh0[nt] = xh0[nt * 8]; bh1[nt] = xh1[nt * 8]; }
#pragma unroll
                for (int nt = 0; nt < 8; ++nt) mma16816(acc[nt], Ah, bh0[nt], bh1[nt]);
            }
        }
        if (MODE >= 2) {
            const float* Pb = g_P + b * 4096;
#pragma unroll
            for (int nt = 0; nt < 8; ++nt) {
                int u0 = nt * 8 + q * 2;
                float2 pa = __ldg((const float2*)(Pb + o_r * 64 + u0));
                float2 pb = __ldg((const float2*)(Pb + o_r8 * 64 + u0));
                acc[nt][0] += pa.x; acc[nt][1] += pa.y;
                acc[nt][2] += pb.x; acc[nt][3] += pb.y;
            }
        } else {
#pragma unroll
            for (int nt = 0; nt < 8; ++nt) {
                acc[nt][0] += bA1; acc[nt][1] += bA1;
                acc[nt][2] += bB1; acc[nt][3] += bB1;
            }
        }
#pragma unroll
        for (int nt = 0; nt < 8; ++nt)
#pragma unroll
            for (int j = 0; j < 4; ++j) acc[nt][j] = fmaxf(acc[nt][j], 0.0f);
        float SA = 0.f, SB = 0.f;
#pragma unroll
        for (int nt = 0; nt < 8; ++nt) { SA += acc[nt][0] + acc[nt][1]; SB += acc[nt][2] + acc[nt][3]; }
        SA += __shfl_xor_sync(0xffffffffu, SA, 1); SA += __shfl_xor_sync(0xffffffffu, SA, 2);
        SB += __shfl_xor_sync(0xffffffffu, SB, 1); SB += __shfl_xor_sync(0xffffffffu, SB, 2);

        if (!FINAL) {
            // post + pair-pack into bH rows 0..31
#pragma unroll
            for (int nt = 0; nt < 8; ++nt) {
                float t0, t1, t2v, t3;
                if (wl >= 2) {
                    t0 = (SA - acc[nt][0]) * inv; t1 = (SA - acc[nt][1]) * inv;
                    t2v = (SB - acc[nt][2]) * inv; t3 = (SB - acc[nt][3]) * inv;
                } else { t0 = acc[nt][0]; t1 = acc[nt][1]; t2v = acc[nt][2]; t3 = acc[nt][3]; }
                float p0 = __shfl_xor_sync(0xffffffffu, t0, 4);
                float p1 = __shfl_xor_sync(0xffffffffu, t1, 4);
                float p2 = __shfl_xor_sync(0xffffffffu, t2v, 4);
                float p3 = __shfl_xor_sync(0xffffffffu, t3, 4);
                float v0a, v0b, v1a, v1b; int c2;
                if (geven) { c2 = o_r >> 1;        v0a = t0; v0b = p0; v1a = t1; v1b = p1; }
                else       { c2 = (o_r8 - 1) >> 1; v0a = p2; v0b = t2v; v1a = p3; v1b = t3; }
                int u0 = nt * 8 + q * 2;
                bH[c2 * 72 + u0]     = packh(v0a, v0b);
                bH[c2 * 72 + u0 + 1] = packh(v1a, v1b);
            }
            BARH(barid);

            // ---- conv2 (KB=4, W2 in regs) ----
            float a2[8][4];
#pragma unroll
            for (int nt = 0; nt < 8; ++nt)
#pragma unroll
                for (int j = 0; j < 4; ++j) a2[nt][j] = 0.f;
#pragma unroll
            for (int kt = 0; kt < 4; ++kt) {
                const uint32_t* xh0 = bH + (kt * 8 + q) * 72 + g;
                const uint32_t* xh1 = bH + (kt * 8 + 4 + q) * 72 + g;
                uint32_t bh0[8], bh1[8];
#pragma unroll
                for (int nt = 0; nt < 8; ++nt) { bh0[nt] = xh0[nt * 8]; bh1[nt] = xh1[nt * 8]; }
#pragma unroll
                for (int nt = 0; nt < 8; ++nt) mma16816(a2[nt], W2r[kt], bh0[nt], bh1[nt]);
            }
#pragma unroll
            for (int nt = 0; nt < 8; ++nt) {
                a2[nt][0] += bA2; a2[nt][1] += bA2;
                a2[nt][2] += bB2; a2[nt][3] += bB2;
            }
            if (RELU2) {
#pragma unroll
                for (int nt = 0; nt < 8; ++nt)
#pragma unroll
                    for (int j = 0; j < 4; ++j) a2[nt][j] = fmaxf(a2[nt][j], 0.0f);
            }
            float S2A = 0.f, S2B = 0.f;
#pragma unroll
            for (int nt = 0; nt < 8; ++nt) { S2A += a2[nt][0] + a2[nt][1]; S2B += a2[nt][2] + a2[nt][3]; }
            S2A += __shfl_xor_sync(0xffffffffu, S2A, 1); S2A += __shfl_xor_sync(0xffffffffu, S2A, 2);
            S2B += __shfl_xor_sync(0xffffffffu, S2B, 1); S2B += __shfl_xor_sync(0xffffffffu, S2B, 2);

            uint32_t* gout = (RELU2 ? g_rP : g_msgsP) + (size_t)ba * 2048;
#pragma unroll
            for (int nt = 0; nt < 8; ++nt) {
                float t0, t1, t2v, t3;
                if (wl >= 2) {
                    t0 = (S2A - a2[nt][0]) * inv; t1 = (S2A - a2[nt][1]) * inv;
                    t2v = (S2B - a2[nt][2]) * inv; t3 = (S2B - a2[nt][3]) * inv;
                } else { t0 = a2[nt][0]; t1 = a2[nt][1]; t2v = a2[nt][2]; t3 = a2[nt][3]; }
                float p0 = __shfl_xor_sync(0xffffffffu, t0, 4);
                float p1 = __shfl_xor_sync(0xffffffffu, t1, 4);
                float p2 = __shfl_xor_sync(0xffffffffu, t2v, 4);
                float p3 = __shfl_xor_sync(0xffffffffu, t3, 4);
                float v0a, v0b, v1a, v1b; int c2;
                if (geven) { c2 = o_r >> 1;        v0a = t0; v0b = p0; v1a = t1; v1b = p1; }
                else       { c2 = (o_r8 - 1) >> 1; v0a = p2; v0b = t2v; v1a = p3; v1b = t3; }
                int u0 = nt * 8 + q * 2;
                uint2 vh; vh.x = packh(v0a, v0b); vh.y = packh(v1a, v1b);
                *(uint2*)(gout + c2 * 64 + u0) = vh;
            }
        } else {
            // FINAL: post in regs, GEMV partial, cross-warp reduce via sRed
#pragma unroll
            for (int nt = 0; nt < 8; ++nt) {
                float f0, f1, f2, f3;
                if (wl >= 2) {
                    f0 = (SA - acc[nt][0]) * inv; f1 = (SA - acc[nt][1]) * inv;
                    f2 = (SB - acc[nt][2]) * inv; f3 = (SB - acc[nt][3]) * inv;
                } else { f0 = acc[nt][0]; f1 = acc[nt][1]; f2 = acc[nt][2]; f3 = acc[nt][3]; }
                float p0 = w2a * f0 + w2b * f2;
                float p1 = w2a * f1 + w2b * f3;
                p0 += __shfl_xor_sync(0xffffffffu, p0, 4);
                p0 += __shfl_xor_sync(0xffffffffu, p0, 8);
                p0 += __shfl_xor_sync(0xffffffffu, p0, 16);
                p1 += __shfl_xor_sync(0xffffffffu, p1, 4);
                p1 += __shfl_xor_sync(0xffffffffu, p1, 8);
                p1 += __shfl_xor_sync(0xffffffffu, p1, 16);
                if (g == 0) {
                    int u0 = nt * 8 + q * 2;
                    sRed[half * 256 + wl * 64 + u0]     = p0;
                    sRed[half * 256 + wl * 64 + u0 + 1] = p1;
                }
            }
            BARH(barid);
            if (t2 < 64) {
                const float* R = sRed + half * 256;
                float sv = R[t2] + R[64 + t2] + R[128 + t2] + R[192 + t2];
                dout[b * 4096 + t2 * 64 + (ba & 63)] = sv + bF;
            }
        }
        o ^= 1;
    }
}

// ---------------- launch -----------------------------------------------------
extern "C" void kernel_launch(void* const* d_in, const int* in_sizes, int n_in,
                              void* d_out, int out_size) {
    (void)in_sizes; (void)n_in; (void)out_size;
    const float* cg      = (const float*)d_in[0];
    const float* phi1_W1 = (const float*)d_in[1];
    const float* phi1_b1 = (const float*)d_in[2];
    const float* phi1_W2 = (const float*)d_in[3];
    const float* phi1_b2 = (const float*)d_in[4];
    const float* phiK_W1 = (const float*)d_in[5];
    const float* phiK_b1 = (const float*)d_in[6];
    const float* phiK_W2 = (const float*)d_in[7];
    const float* phiK_b2 = (const float*)d_in[8];
    const float* g1_W1   = (const float*)d_in[9];
    const float* g1_b1   = (const float*)d_in[10];
    const float* g1_W2   = (const float*)d_in[11];
    const float* g1_b2   = (const float*)d_in[12];
    const float* gK_W1   = (const float*)d_in[13];
    const float* gK_b1   = (const float*)d_in[14];
    const float* gK_W2   = (const float*)d_in[15];
    const float* gK_b2   = (const float*)d_in[16];
    const float* g5_W1   = (const float*)d_in[17];
    const float* g5_b1   = (const float*)d_in[18];
    const float* g5_W2   = (const float*)d_in[19];
    const float* g5_b2   = (const float*)d_in[20];
    float* out = (float*)d_out;

    auto smem_bytes = [](int KB1, bool fin) {
        int XR = (KB1 * 8 < 32) ? 32 : KB1 * 8;
        int u32s = KB1 * 512 + 4 * XR * 72 + (fin ? 512 : 0) + 16;
        return u32s * 4;
    };
    const int SM1 = smem_bytes(1, false);
    const int SM5 = smem_bytes(5, false);
    const int SM8 = smem_bytes(8, false);
    const int SMF = smem_bytes(8, true);

    cudaFuncSetAttribute(layer_kernel<1, 0, false>, cudaFuncAttributeMaxDynamicSharedMemorySize, SM1);
    cudaFuncSetAttribute(layer_kernel<5, 1, false>, cudaFuncAttributeMaxDynamicSharedMemorySize, SM5);
    cudaFuncSetAttribute(layer_kernel<5, 2, false>, cudaFuncAttributeMaxDynamicSharedMemorySize, SM5);
    cudaFuncSetAttribute(layer_kernel<8, 3, false>, cudaFuncAttributeMaxDynamicSharedMemorySize, SM8);
    cudaFuncSetAttribute(layer_kernel<8, 3, true>,  cudaFuncAttributeMaxDynamicSharedMemorySize, SMF);

    prep_kernel<<<19, 256>>>(phi1_W1, phi1_W2, phiK_W1, phiK_W2, g1_W1, g1_W2, gK_W1, gK_W2, g5_W1);
    cgt_kernel<<<128, 256>>>(cg);

    const int G = 296;

    layer_kernel<1, 0, false><<<G, 256, SM1>>>(phi1_b1, phi1_b2, OFF_PHI1_W1F, OFF_PHI1_W2F, nullptr, nullptr);
    asum_kernel<<<1024, 256>>>();
    pP_kernel<<<128, 256>>>(g1_W1, g1_b1, 65, 1);
    layer_kernel<5, 2, false><<<G, 256, SM5>>>(nullptr, g1_b2, OFF_G1_W1F, OFF_G1_W2F, nullptr, nullptr);

    for (int i = 0; i < 4; ++i) {
        layer_kernel<5, 1, false><<<G, 256, SM5>>>(phiK_b1 + i * 64, phiK_b2 + i * 64,
                                                   OFF_PHIK_W1F + i * 2560, OFF_PHIK_W2F + i * 2048,
                                                   nullptr, nullptr);
        asum_kernel<<<1024, 256>>>();
        if (i < 3) {
            pP_kernel<<<128, 256>>>(gK_W1 + i * 8192, gK_b1 + i * 64, 128, 64);
            layer_kernel<8, 3, false><<<G, 256, SM8>>>(nullptr, gK_b2 + i * 64,
                                                       OFF_GK_W1F + i * 4096, OFF_GK_W2F + i * 2048,
                                                       nullptr, nullptr);
        } else {
            pP_kernel<<<128, 256>>>(g5_W1, g5_b1, 128, 64);
            layer_kernel<8, 3, true><<<G, 256, SMF>>>(nullptr, g5_b2,
                                                      OFF_G5_W1F, 0, g5_W2, out);
        }
    }
}